// round 2
// baseline (speedup 1.0000x reference)
#include <cuda_runtime.h>

// Problem constants (GraphAttentionLayer: B=4, N=16384, E=262144, F=64)
#define FD   64
#define MAXB 4
#define MAXN 16384
#define MAXE 262144

#define LRELU_ALPHA 0.01f
#define EXP_CLAMP   1000000.0f
#define DENOM_EPS   1e-10f

// ---------------- device scratch (no allocations allowed) ----------------
__device__ float g_Wh[(size_t)MAXB * MAXN * FD];        // 16 MB
__device__ float g_sc[MAXB * MAXN];                     // Wh . a[0:64]
__device__ float g_sn[MAXB * MAXN];                     // Wh . a[64:128]
__device__ float g_denom[MAXB * MAXN];                  // segment sums of x_exp
__device__ float g_xexp[(size_t)MAXB * MAXE];           // masked clipped exp

// ---------------- init: zero output accumulator + denom ----------------
__global__ __launch_bounds__(256)
void init_kernel(float* __restrict__ out, int nOut4, int nDenom) {
    int i = blockIdx.x * blockDim.x + threadIdx.x;
    int stride = gridDim.x * blockDim.x;
    float4 z = make_float4(0.f, 0.f, 0.f, 0.f);
    for (int k = i; k < nOut4; k += stride)
        reinterpret_cast<float4*>(out)[k] = z;
    for (int k = i; k < nDenom; k += stride)
        g_denom[k] = 0.f;
}

// ---------------- GEMM: Wh = h @ W^T, plus sc/sn epilogue ----------------
// 256 threads / block, 64 rows / block. 4 threads per row, 16 outputs each.
__global__ __launch_bounds__(256)
void gemm_kernel(const float* __restrict__ h, const float* __restrict__ W,
                 const float* __restrict__ a, int R) {
    __shared__ float sWt[64][68];   // W transposed: sWt[f][o], padded (272B rows, 16B aligned)
    __shared__ float sh[64][65];    // h tile, padded for conflict-free column reads
    __shared__ float sa[2 * FD];

    int tid = threadIdx.x;
    int row0 = blockIdx.x * 64;

    for (int i = tid; i < 64 * 64; i += 256) {
        int o = i >> 6, f = i & 63;
        sWt[f][o] = W[i];
    }
    if (tid < 2 * FD) sa[tid] = a[tid];
    for (int i = tid; i < 64 * 64; i += 256) {
        int r = i >> 6, f = i & 63;
        sh[r][f] = h[(size_t)(row0 + r) * FD + f];
    }
    __syncthreads();

    int r  = tid >> 2;          // row within tile: 0..63
    int og = (tid & 3) * 16;    // output group start: 0/16/32/48

    float acc[16];
#pragma unroll
    for (int j = 0; j < 16; j++) acc[j] = 0.f;

#pragma unroll
    for (int f = 0; f < 64; f++) {
        float hv = sh[r][f];
        const float4* wrow = reinterpret_cast<const float4*>(&sWt[f][og]);
#pragma unroll
        for (int j4 = 0; j4 < 4; j4++) {
            float4 w = wrow[j4];
            acc[j4 * 4 + 0] += hv * w.x;
            acc[j4 * 4 + 1] += hv * w.y;
            acc[j4 * 4 + 2] += hv * w.z;
            acc[j4 * 4 + 3] += hv * w.w;
        }
    }

    // epilogue: partial dots with attention vector halves
    float scp = 0.f, snp = 0.f;
#pragma unroll
    for (int j = 0; j < 16; j++) {
        scp += acc[j] * sa[og + j];
        snp += acc[j] * sa[FD + og + j];
    }
    // reduce across the 4 consecutive lanes owning this row
    scp += __shfl_xor_sync(0xffffffffu, scp, 1);
    scp += __shfl_xor_sync(0xffffffffu, scp, 2);
    snp += __shfl_xor_sync(0xffffffffu, snp, 1);
    snp += __shfl_xor_sync(0xffffffffu, snp, 2);

    int row = row0 + r;
    float4* out4 = reinterpret_cast<float4*>(&g_Wh[(size_t)row * FD + og]);
#pragma unroll
    for (int j4 = 0; j4 < 4; j4++)
        out4[j4] = make_float4(acc[j4*4+0], acc[j4*4+1], acc[j4*4+2], acc[j4*4+3]);

    if ((tid & 3) == 0) {
        g_sc[row] = scp;
        g_sn[row] = snp;
    }
}

// ---------------- edge pass 1: x_exp + denominator segment sum ----------------
__global__ __launch_bounds__(256)
void edge1_kernel(const int2* __restrict__ edge, const float* __restrict__ ew,
                  const int* __restrict__ edge_num, int N, int E) {
    int b = blockIdx.y;
    int e = blockIdx.x * blockDim.x + threadIdx.x;
    if (e >= E) return;
    size_t idx = (size_t)b * E + e;
    int en = edge_num[b];
    float x = 0.f;
    if (e < en) {
        int2 ed = edge[idx];
        float s = g_sc[b * N + ed.x] + g_sn[b * N + ed.y];
        float t = ew[idx] * s;
        float att1 = (t >= 0.f) ? t : LRELU_ALPHA * t;        // leaky_relu
        x = fminf(expf(att1), EXP_CLAMP);                     // clip(exp, 0, 1e6)
        atomicAdd(&g_denom[b * N + ed.x], x);                 // -> RED.E.ADD.F32
    }
    g_xexp[idx] = x;
}

// ---------------- edge pass 2: scatter att * Wh[nbr] into output ----------------
// 16 threads per edge; each thread handles a float4 of the 64-wide feature row.
__global__ __launch_bounds__(256)
void edge2_kernel(const int2* __restrict__ edge, float* __restrict__ hp,
                  int N, int E) {
    int b   = blockIdx.y;
    int sub = threadIdx.x & 15;
    int e   = blockIdx.x * (blockDim.x >> 4) + (threadIdx.x >> 4);
    if (e >= E) return;
    size_t idx = (size_t)b * E + e;

    float x = 0.f, d = 0.f;
    int ctr = 0, nbr = 0;
    if (sub == 0) {
        int2 ed = edge[idx];
        ctr = ed.x;
        nbr = ed.y;
        x = g_xexp[idx];
        d = g_denom[b * N + ed.x];
    }
    // broadcast leader values within each 16-lane segment
    x   = __shfl_sync(0xffffffffu, x,   0, 16);
    d   = __shfl_sync(0xffffffffu, d,   0, 16);
    ctr = __shfl_sync(0xffffffffu, ctr, 0, 16);
    nbr = __shfl_sync(0xffffffffu, nbr, 0, 16);

    if (x == 0.f) return;   // masked edge (e >= edge_num[b])

    float att = x / (DENOM_EPS + d);
    const float4 w = reinterpret_cast<const float4*>(g_Wh)[((size_t)b * N + nbr) * 16 + sub];
    float vx = w.x * att, vy = w.y * att, vz = w.z * att, vw = w.w * att;
    float* dst = hp + ((size_t)b * N + ctr) * FD + sub * 4;
    // sm_90+ vectorized reduction: one L2 atomic op per 16 bytes
    asm volatile("red.global.add.v4.f32 [%0], {%1, %2, %3, %4};"
                 :: "l"(dst), "f"(vx), "f"(vy), "f"(vz), "f"(vw) : "memory");
}

// ---------------- final: in-place ReLU ----------------
__global__ __launch_bounds__(256)
void relu_kernel(float* __restrict__ out, int n4) {
    int i = blockIdx.x * blockDim.x + threadIdx.x;
    if (i >= n4) return;
    float4 v = reinterpret_cast<float4*>(out)[i];
    v.x = fmaxf(v.x, 0.f);
    v.y = fmaxf(v.y, 0.f);
    v.z = fmaxf(v.z, 0.f);
    v.w = fmaxf(v.w, 0.f);
    reinterpret_cast<float4*>(out)[i] = v;
}

// ---------------- launch ----------------
extern "C" void kernel_launch(void* const* d_in, const int* in_sizes, int n_in,
                              void* d_out, int out_size) {
    const float* h   = (const float*)d_in[0];
    const int2*  edg = (const int2*) d_in[1];
    const int*   en  = (const int*)  d_in[2];
    const float* ew  = (const float*)d_in[3];
    const float* W   = (const float*)d_in[4];
    const float* a   = (const float*)d_in[5];
    float* out = (float*)d_out;

    int B = in_sizes[2];                 // edge_num has B elements
    int E = in_sizes[3] / B;             // edge_weight is B*E
    int N = in_sizes[0] / (B * FD);      // h is B*N*F
    int R = B * N;

    init_kernel<<<256, 256>>>(out, out_size / 4, R);
    gemm_kernel<<<R / 64, 256>>>(h, W, a, R);

    dim3 g1((E + 255) / 256, B);
    edge1_kernel<<<g1, 256>>>(edg, ew, en, N, E);

    dim3 g2((E + 15) / 16, B);
    edge2_kernel<<<g2, 256>>>(edg, out, N, E);

    relu_kernel<<<(out_size / 4 + 255) / 256, 256>>>(out, out_size / 4);
}